// round 3
// baseline (speedup 1.0000x reference)
#include <cuda_runtime.h>

#define BB 8
#define CC 32
#define HH 64
#define VOCABN 4096
#define NELEM (BB*CC*HH*HH)   // 131072
#define NSCALE 7

// -------- scratch (static __device__, no allocations) --------
__device__ float g_cbn[VOCABN*CC];            // normalized codebook
__device__ float g_frest[NELEM];              // running residual
__device__ float g_rest[BB*CC*32*32];         // downsampled residual (max pn=32)
__device__ float g_hup[NELEM];                // upsampled gathered codes
__device__ unsigned long long g_keys[BB*HH*HH]; // packed (sim,idx) argmax keys
__device__ float g_partials[NSCALE*256];      // per-block loss partials

__device__ __forceinline__ unsigned f2ord(float f) {
    unsigned u = __float_as_uint(f);
    return (u & 0x80000000u) ? ~u : (u | 0x80000000u);
}

// -------- codebook row-normalize (warp per row) --------
__global__ void k_cbn(const float* __restrict__ cb) {
    int warp = (blockIdx.x*blockDim.x + threadIdx.x) >> 5;
    int lane = threadIdx.x & 31;
    if (warp >= VOCABN) return;
    float v = cb[warp*CC + lane];
    float s = v*v;
    #pragma unroll
    for (int o = 16; o; o >>= 1) s += __shfl_xor_sync(0xffffffffu, s, o);
    g_cbn[warp*CC + lane] = v / sqrtf(s);
}

// -------- area downsample, thread per output (k <= 4) --------
__global__ void k_ds_thread(const float* __restrict__ src, int pn, int k) {
    int i = blockIdx.x*blockDim.x + threadIdx.x;
    int total = BB*CC*pn*pn;
    if (i >= total) return;
    int q = i % pn; int p = (i/pn) % pn; int bc = i/(pn*pn);
    const float* s = src + bc*HH*HH + p*k*HH + q*k;
    float acc = 0.f;
    for (int yy = 0; yy < k; yy++)
        for (int xx = 0; xx < k; xx++) acc += s[yy*HH + xx];
    g_rest[i] = acc * (1.f/(float)(k*k));
}

// -------- area downsample, warp per output (k >= 8) --------
__global__ void k_ds_warp(const float* __restrict__ src, int pn, int k) {
    int gw = (blockIdx.x*blockDim.x + threadIdx.x) >> 5;
    int lane = threadIdx.x & 31;
    int total = BB*CC*pn*pn;
    if (gw >= total) return;
    int q = gw % pn; int p = (gw/pn) % pn; int bc = gw/(pn*pn);
    const float* s = src + bc*HH*HH + p*k*HH + q*k;
    int kk = k*k;
    float acc = 0.f;
    for (int t = lane; t < kk; t += 32) acc += s[(t/k)*HH + (t % k)];
    #pragma unroll
    for (int o = 16; o; o >>= 1) acc += __shfl_xor_sync(0xffffffffu, acc, o);
    if (lane == 0) g_rest[gw] = acc * (1.f/(float)kk);
}

// -------- argmax, block per vector (tiny N) --------
__global__ void k_argmax_small(const float* __restrict__ rest, int pnpn) {
    __shared__ float vsh[CC];
    __shared__ unsigned long long kred[512];
    int n = blockIdx.x;
    int tid = threadIdx.x;
    if (tid < CC) {
        int b = n / pnpn, r = n % pnpn;
        vsh[tid] = rest[(b*CC + tid)*pnpn + r];
    }
    __syncthreads();
    float v[CC];
    #pragma unroll
    for (int c = 0; c < CC; c++) v[c] = vsh[c];
    float best = -1e30f; int bidx = 0;
    for (int code = tid; code < VOCABN; code += 512) {
        const float4* row = (const float4*)(g_cbn + code*CC);
        float a0=0.f, a1=0.f, a2=0.f, a3=0.f;
        #pragma unroll
        for (int cc = 0; cc < 8; cc++) {
            float4 r = row[cc];
            a0 += v[4*cc+0]*r.x; a1 += v[4*cc+1]*r.y;
            a2 += v[4*cc+2]*r.z; a3 += v[4*cc+3]*r.w;
        }
        float acc = (a0+a1)+(a2+a3);
        if (acc > best) { best = acc; bidx = code; }
    }
    kred[tid] = ((unsigned long long)f2ord(best) << 32) | (unsigned long long)(0xFFFFFFFFu - (unsigned)bidx);
    __syncthreads();
    #pragma unroll
    for (int s = 256; s > 0; s >>= 1) {
        if (tid < s) { unsigned long long o = kred[tid+s]; if (o > kred[tid]) kred[tid] = o; }
        __syncthreads();
    }
    if (tid == 0) g_keys[n] = kred[0];
}

// -------- argmax, thread per vector, codes split across blockIdx.y --------
__global__ void k_argmax_big(const float* __restrict__ rest, int N, int pnpn, int chunk) {
    __shared__ float scb[256*CC];  // 32 KB tile
    int n = blockIdx.x*128 + threadIdx.x;
    int c0 = blockIdx.y * chunk;
    float v[CC];
    bool active = (n < N);
    if (active) {
        int b = n / pnpn, r = n % pnpn;
        const float* s = rest + b*CC*pnpn + r;
        #pragma unroll
        for (int c = 0; c < CC; c++) v[c] = s[c*pnpn];
    }
    float best = -1e30f; int bidx = 0;
    for (int t0 = 0; t0 < chunk; t0 += 256) {
        int tile = min(256, chunk - t0);
        __syncthreads();
        const float4* src4 = (const float4*)(g_cbn + (c0 + t0)*CC);
        float4* dst4 = (float4*)scb;
        for (int i = threadIdx.x; i < tile*8; i += 128) dst4[i] = src4[i];
        __syncthreads();
        if (active) {
            for (int j = 0; j < tile; j++) {
                const float4* row = (const float4*)(scb + j*CC);
                float a0=0.f, a1=0.f, a2=0.f, a3=0.f;
                #pragma unroll
                for (int cc = 0; cc < 8; cc++) {
                    float4 r = row[cc];
                    a0 += v[4*cc+0]*r.x; a1 += v[4*cc+1]*r.y;
                    a2 += v[4*cc+2]*r.z; a3 += v[4*cc+3]*r.w;
                }
                float acc = (a0+a1)+(a2+a3);
                if (acc > best) { best = acc; bidx = c0 + t0 + j; }
            }
        }
    }
    if (active) {
        unsigned long long key = ((unsigned long long)f2ord(best) << 32)
                               | (unsigned long long)(0xFFFFFFFFu - (unsigned)bidx);
        atomicMax(g_keys + n, key);
    }
}

// -------- bicubic weight (PyTorch A=-0.75) --------
__device__ __forceinline__ float cubicw(float t) {
    t = fabsf(t);
    float t2 = t*t, t3 = t2*t;
    if (t <= 1.f) return 1.25f*t3 - 2.25f*t2 + 1.f;
    if (t < 2.f)  return -0.75f*t3 + 3.75f*t2 - 6.f*t + 3.f;
    return 0.f;
}

// -------- gather + bicubic upsample (or direct gather for pn==64) --------
__global__ void k_up(const float* __restrict__ cb, int pn) {
    int c = threadIdx.x;                    // 0..31 (channel)
    int X = blockIdx.x*8 + threadIdx.y;     // 0..63
    int Y = blockIdx.y;                     // 0..63
    int b = blockIdx.z;                     // 0..7
    float out;
    if (pn == HH) {
        int n = (b*HH + Y)*HH + X;
        int idx = (int)(0xFFFFFFFFu - (unsigned)(g_keys[n] & 0xFFFFFFFFull));
        out = cb[idx*CC + c];
    } else {
        float scale = (float)pn / (float)HH;
        float fy = (Y + 0.5f)*scale - 0.5f;
        float fx = (X + 0.5f)*scale - 0.5f;
        int y0 = (int)floorf(fy), x0 = (int)floorf(fx);
        float wy[4], wx[4];
        #pragma unroll
        for (int t = 0; t < 4; t++) {
            wy[t] = cubicw(fy - (float)(y0 - 1 + t));
            wx[t] = cubicw(fx - (float)(x0 - 1 + t));
        }
        float acc = 0.f;
        #pragma unroll
        for (int ty = 0; ty < 4; ty++) {
            int py = min(max(y0 - 1 + ty, 0), pn - 1);
            float rowacc = 0.f;
            #pragma unroll
            for (int tx = 0; tx < 4; tx++) {
                int px = min(max(x0 - 1 + tx, 0), pn - 1);
                int n = (b*pn + py)*pn + px;
                int idx = (int)(0xFFFFFFFFu - (unsigned)(g_keys[n] & 0xFFFFFFFFull));
                rowacc += wx[tx]*cb[idx*CC + c];
            }
            acc += wy[ty]*rowacc;
        }
        out = acc;
    }
    g_hup[((b*CC + c)*HH + Y)*HH + X] = out;
}

// -------- conv3x3 + Phi blend + f_hat/f_rest update + loss partial --------
// grid (16 ytiles, 8 b, 2 oc-halves), block (64,4), dynamic smem.
#define CONV_SMEM ((32*6*66 + 16*32*9 + 16 + 256)*4)

__global__ void k_conv(const float* __restrict__ f, const float* __restrict__ phi_w,
                       const float* __restrict__ phi_b, float* __restrict__ fhat,
                       int kphi, int si) {
    extern __shared__ float sh[];
    float* tile = sh;                 // 32*6*66 = 12672
    float* wsh  = tile + 32*6*66;     // 16*32*9 = 4608
    float* bsh  = wsh + 16*32*9;      // 16
    float* red  = bsh + 16;           // 256
    int tx = threadIdx.x, ty = threadIdx.y;
    int tid = ty*64 + tx;
    int y0 = blockIdx.x*4;
    int b  = blockIdx.y;
    int ocb = blockIdx.z*16;

    const float* wsrc = phi_w + (size_t)(kphi*32 + ocb)*32*9;
    for (int i = tid; i < 16*32*9; i += 256) wsh[i] = wsrc[i];
    if (tid < 16) bsh[tid] = phi_b[kphi*32 + ocb + tid];

    for (int i = tid; i < 32*6*66; i += 256) {
        int xx = i % 66; int yy = (i/66) % 6; int ic = i/(66*6);
        int gy = y0 - 1 + yy, gx = xx - 1;
        float val = 0.f;
        if ((unsigned)gy < 64u && (unsigned)gx < 64u)
            val = g_hup[((b*CC + ic)*HH + gy)*HH + gx];
        tile[i] = val;
    }
    __syncthreads();

    float acc[16];
    #pragma unroll
    for (int o = 0; o < 16; o++) acc[o] = 0.f;
    for (int ic = 0; ic < 32; ic++) {
        const float* tb = tile + (ic*6 + ty)*66 + tx;
        float t0 = tb[0],   t1 = tb[1],   t2 = tb[2];
        float t3 = tb[66],  t4 = tb[67],  t5 = tb[68];
        float t6 = tb[132], t7 = tb[133], t8 = tb[134];
        #pragma unroll
        for (int o = 0; o < 16; o++) {
            const float* w = wsh + (o*32 + ic)*9;
            acc[o] += w[0]*t0 + w[1]*t1 + w[2]*t2
                    + w[3]*t3 + w[4]*t4 + w[5]*t5
                    + w[6]*t6 + w[7]*t7 + w[8]*t8;
        }
    }

    float ss = 0.f;
    int y = y0 + ty, x = tx;
    #pragma unroll
    for (int o = 0; o < 16; o++) {
        int oc = ocb + o;
        float h  = tile[(oc*6 + ty + 1)*66 + tx + 1];
        float hp = 0.5f*h + 0.5f*(acc[o] + bsh[o]);
        int gi = ((b*CC + oc)*HH + y)*HH + x;
        float fv = f[gi];
        float fh = (si == 0 ? 0.f : fhat[gi]) + hp;
        fhat[gi] = fh;
        g_frest[gi] = fv - fh;
        float d = fh - fv;
        ss += d*d;
    }

    red[tid] = ss;
    __syncthreads();
    #pragma unroll
    for (int s = 128; s > 0; s >>= 1) {
        if (tid < s) red[tid] += red[tid + s];
        __syncthreads();
    }
    if (tid == 0) {
        int bl = (blockIdx.z*8 + blockIdx.y)*16 + blockIdx.x;
        g_partials[si*256 + bl] = red[0];
    }
}

// -------- final loss reduce (deterministic fixed order) --------
__global__ void k_final(float* __restrict__ out) {
    __shared__ float red[128];
    int tid = threadIdx.x;
    float s = 0.f;
    for (int i = tid; i < NSCALE*256; i += 128) s += g_partials[i];
    red[tid] = s;
    __syncthreads();
    #pragma unroll
    for (int st = 64; st > 0; st >>= 1) {
        if (tid < st) red[tid] += red[tid + st];
        __syncthreads();
    }
    if (tid == 0) {
        float T = red[0];
        out[NELEM]     = T / (7.f * (float)NELEM);
        out[NELEM + 1] = 0.25f * T / (float)NELEM;
    }
}

// -------- host --------
extern "C" void kernel_launch(void* const* d_in, const int* in_sizes, int n_in,
                              void* d_out, int out_size) {
    const float* f    = (const float*)d_in[0];
    const float* cb   = (const float*)d_in[1];
    const float* phiw = (const float*)d_in[2];
    const float* phib = (const float*)d_in[3];
    float* out = (float*)d_out;

    cudaFuncSetAttribute(k_conv, cudaFuncAttributeMaxDynamicSharedMemorySize, CONV_SMEM);

    void *keysPtr = nullptr, *frestPtr = nullptr, *restPtr = nullptr;
    cudaGetSymbolAddress(&keysPtr, g_keys);
    cudaGetSymbolAddress(&frestPtr, g_frest);
    cudaGetSymbolAddress(&restPtr, g_rest);

    k_cbn<<<(VOCABN*32 + 255)/256, 256>>>(cb);

    const int pns[NSCALE]    = {1, 2, 4, 8, 16, 32, 64};
    // PHI ticks in float64: ticks[1]=0.36111111111111109568, ticks[2]=0.63888888888888886265
    // -> si=3 (key 0.5) resolves to phi index 2 (fp tie-break), NOT 1.
    const int phiIdx[NSCALE] = {0, 0, 1, 2, 2, 3, 3};
    const int chunks[NSCALE] = {0, 0, 0, 128, 256, 512, 2048};

    for (int si = 0; si < NSCALE; si++) {
        int pn = pns[si]; int pnpn = pn*pn; int N = BB*pnpn; int k = HH/pn;
        const float* src = (si == 0) ? f : (const float*)frestPtr;
        const float* restp;
        if (pn == HH) {
            restp = src;  // last scale: residual used directly
        } else {
            int outs = N*CC;
            if (k <= 4) k_ds_thread<<<(outs + 255)/256, 256>>>(src, pn, k);
            else        k_ds_warp<<<(outs*32 + 255)/256, 256>>>(src, pn, k);
            restp = (const float*)restPtr;
        }
        if (N <= 128) {
            k_argmax_small<<<N, 512>>>(restp, pnpn);
        } else {
            cudaMemsetAsync(keysPtr, 0, (size_t)N*sizeof(unsigned long long));
            dim3 g((N + 127)/128, VOCABN/chunks[si]);
            k_argmax_big<<<g, 128>>>(restp, N, pnpn, chunks[si]);
        }
        k_up<<<dim3(8, 64, 8), dim3(32, 8)>>>(cb, pn);
        k_conv<<<dim3(16, 8, 2), dim3(64, 4), CONV_SMEM>>>(f, phiw, phib, out, phiIdx[si], si);
    }
    k_final<<<1, 128>>>(out);
}

// round 5
// speedup vs baseline: 1.2618x; 1.2618x over previous
#include <cuda_runtime.h>

#define BB 8
#define CC 32
#define HH 64
#define VOCABN 4096
#define NELEM (BB*CC*HH*HH)   // 131072
#define NSCALE 7

typedef unsigned long long ull;

// -------- scratch (static __device__, no allocations) --------
__device__ float g_cbn[VOCABN*CC];            // normalized codebook, PAIR-INTERLEAVED:
                                              // g_cbn[p*64 + 2*c + h] = cbn[2p+h][c]
__device__ float g_frest[NELEM];              // running residual
__device__ float g_rest[BB*CC*32*32];         // downsampled residual (max pn=32)
__device__ float g_hup[NELEM];                // upsampled gathered codes
__device__ ull g_keys[BB*HH*HH];              // packed (sim,idx) argmax keys
__device__ float g_partials[NSCALE*256];      // per-block loss partials

// -------- f32x2 packed math (sm_100+) --------
__device__ __forceinline__ ull fma2(ull a, ull b, ull c) {
    ull d; asm("fma.rn.f32x2 %0, %1, %2, %3;" : "=l"(d) : "l"(a), "l"(b), "l"(c)); return d;
}
__device__ __forceinline__ ull add2(ull a, ull b) {
    ull d; asm("add.rn.f32x2 %0, %1, %2;" : "=l"(d) : "l"(a), "l"(b)); return d;
}
__device__ __forceinline__ ull pack2(float lo, float hi) {
    ull d; asm("mov.b64 %0, {%1, %2};" : "=l"(d) : "f"(lo), "f"(hi)); return d;
}
__device__ __forceinline__ void unpack2(ull v, float& lo, float& hi) {
    asm("mov.b64 {%0, %1}, %2;" : "=f"(lo), "=f"(hi) : "l"(v));
}

__device__ __forceinline__ unsigned f2ord(float f) {
    unsigned u = __float_as_uint(f);
    return (u & 0x80000000u) ? ~u : (u | 0x80000000u);
}

// -------- codebook row-normalize -> pair-interleaved layout --------
__global__ void k_cbn(const float* __restrict__ cb) {
    int row = (blockIdx.x*blockDim.x + threadIdx.x) >> 5;
    int lane = threadIdx.x & 31;
    if (row >= VOCABN) return;
    float v = cb[row*CC + lane];
    float s = v*v;
    #pragma unroll
    for (int o = 16; o; o >>= 1) s += __shfl_xor_sync(0xffffffffu, s, o);
    int p = row >> 1, h = row & 1;
    g_cbn[p*64 + 2*lane + h] = v / sqrtf(s);
}

// -------- area downsample, thread per output (k <= 4) --------
__global__ void k_ds_thread(const float* __restrict__ src, int pn, int k) {
    int i = blockIdx.x*blockDim.x + threadIdx.x;
    int total = BB*CC*pn*pn;
    if (i >= total) return;
    int q = i % pn; int p = (i/pn) % pn; int bc = i/(pn*pn);
    const float* s = src + bc*HH*HH + p*k*HH + q*k;
    float acc = 0.f;
    for (int yy = 0; yy < k; yy++)
        for (int xx = 0; xx < k; xx++) acc += s[yy*HH + xx];
    g_rest[i] = acc * (1.f/(float)(k*k));
}

// -------- area downsample, warp per output (k >= 8) --------
__global__ void k_ds_warp(const float* __restrict__ src, int pn, int k) {
    int gw = (blockIdx.x*blockDim.x + threadIdx.x) >> 5;
    int lane = threadIdx.x & 31;
    int total = BB*CC*pn*pn;
    if (gw >= total) return;
    int q = gw % pn; int p = (gw/pn) % pn; int bc = gw/(pn*pn);
    const float* s = src + bc*HH*HH + p*k*HH + q*k;
    int kk = k*k;
    float acc = 0.f;
    for (int t = lane; t < kk; t += 32) acc += s[(t/k)*HH + (t % k)];
    #pragma unroll
    for (int o = 16; o; o >>= 1) acc += __shfl_xor_sync(0xffffffffu, acc, o);
    if (lane == 0) g_rest[gw] = acc * (1.f/(float)kk);
}

// -------- pair dot-product core: 32 channels vs packed code pair --------
__device__ __forceinline__ void pair_sim(const ull* __restrict__ vd,
                                         const float* __restrict__ pairrow,
                                         float& lo, float& hi) {
    const ulonglong2* row2 = (const ulonglong2*)pairrow;
    ull a0 = 0ull, a1 = 0ull, a2 = 0ull, a3 = 0ull;
    #pragma unroll
    for (int cc = 0; cc < 8; cc++) {
        ulonglong2 r0 = row2[2*cc];
        ulonglong2 r1 = row2[2*cc+1];
        a0 = fma2(vd[4*cc+0], r0.x, a0);
        a1 = fma2(vd[4*cc+1], r0.y, a1);
        a2 = fma2(vd[4*cc+2], r1.x, a2);
        a3 = fma2(vd[4*cc+3], r1.y, a3);
    }
    ull s = add2(add2(a0, a1), add2(a2, a3));
    unpack2(s, lo, hi);
}

// -------- argmax, block per vector (tiny N) --------
__global__ void k_argmax_small(const float* __restrict__ rest, int pnpn) {
    __shared__ float vsh[CC];
    __shared__ ull kred[512];
    int n = blockIdx.x;
    int tid = threadIdx.x;
    if (tid < CC) {
        int b = n / pnpn, r = n % pnpn;
        vsh[tid] = rest[(b*CC + tid)*pnpn + r];
    }
    __syncthreads();
    ull vd[CC];
    #pragma unroll
    for (int c = 0; c < CC; c++) { float v = vsh[c]; vd[c] = pack2(v, v); }
    float best = -1e30f; int bidx = 0;
    for (int p = tid; p < VOCABN/2; p += 512) {
        float lo, hi;
        pair_sim(vd, g_cbn + p*64, lo, hi);
        if (lo > best) { best = lo; bidx = 2*p; }
        if (hi > best) { best = hi; bidx = 2*p + 1; }
    }
    kred[tid] = ((ull)f2ord(best) << 32) | (ull)(0xFFFFFFFFu - (unsigned)bidx);
    __syncthreads();
    #pragma unroll
    for (int s = 256; s > 0; s >>= 1) {
        if (tid < s) { ull o = kred[tid+s]; if (o > kred[tid]) kred[tid] = o; }
        __syncthreads();
    }
    if (tid == 0) g_keys[n] = kred[0];
}

// -------- argmax, thread per vector, codes split across blockIdx.y --------
// REQUIREMENT: chunk must be a multiple of 256 (full tiles only).
__global__ void k_argmax_big(const float* __restrict__ rest, int N, int pnpn, int chunk) {
    __shared__ float scb[256*CC];  // 32 KB tile: 128 pairs x 64 floats
    int n = blockIdx.x*128 + threadIdx.x;
    int c0 = blockIdx.y * chunk;
    ull vd[CC];
    bool active = (n < N);
    if (active) {
        int b = n / pnpn, r = n % pnpn;
        const float* s = rest + b*CC*pnpn + r;
        #pragma unroll
        for (int c = 0; c < CC; c++) { float v = s[c*pnpn]; vd[c] = pack2(v, v); }
    } else {
        #pragma unroll
        for (int c = 0; c < CC; c++) vd[c] = 0ull;
    }
    float best = -1e30f; int bidx = 0;
    for (int t0 = 0; t0 < chunk; t0 += 256) {
        __syncthreads();
        // pair-interleaved layout is contiguous: codes [c0+t0, c0+t0+256) = floats [(c0+t0)*32, ...)
        const float4* src4 = (const float4*)(g_cbn + (c0 + t0)*CC);
        float4* dst4 = (float4*)scb;
        #pragma unroll 4
        for (int i = threadIdx.x; i < 256*8; i += 128) dst4[i] = src4[i];
        __syncthreads();
        #pragma unroll 2
        for (int j2 = 0; j2 < 128; j2++) {
            float lo, hi;
            pair_sim(vd, scb + j2*64, lo, hi);
            int code = c0 + t0 + 2*j2;
            if (lo > best) { best = lo; bidx = code; }
            if (hi > best) { best = hi; bidx = code + 1; }
        }
    }
    if (active) {
        ull key = ((ull)f2ord(best) << 32) | (ull)(0xFFFFFFFFu - (unsigned)bidx);
        atomicMax(g_keys + n, key);
    }
}

// -------- bicubic weight (PyTorch A=-0.75) --------
__device__ __forceinline__ float cubicw(float t) {
    t = fabsf(t);
    float t2 = t*t, t3 = t2*t;
    if (t <= 1.f) return 1.25f*t3 - 2.25f*t2 + 1.f;
    if (t < 2.f)  return -0.75f*t3 + 3.75f*t2 - 6.f*t + 3.f;
    return 0.f;
}

// -------- gather + bicubic upsample (or direct gather for pn==64) --------
__global__ void k_up(const float* __restrict__ cb, int pn) {
    __shared__ float swx[8][4];
    __shared__ int   spx[8][4];
    __shared__ float swy[4];
    __shared__ int   spy[4];
    int c = threadIdx.x;                    // 0..31 (channel)
    int tyi = threadIdx.y;                  // 0..7
    int X = blockIdx.x*8 + tyi;             // 0..63
    int Y = blockIdx.y;                     // 0..63
    int b = blockIdx.z;                     // 0..7
    int tid = tyi*32 + c;
    float out;
    if (pn == HH) {
        int n = (b*HH + Y)*HH + X;
        int idx = (int)(0xFFFFFFFFu - (unsigned)(g_keys[n] & 0xFFFFFFFFull));
        out = cb[idx*CC + c];
    } else {
        if (tid < 9) {
            float scale = (float)pn / (float)HH;
            int pos = (tid < 8) ? (blockIdx.x*8 + tid) : Y;
            float fz = (pos + 0.5f)*scale - 0.5f;
            int z0 = (int)floorf(fz);
            #pragma unroll
            for (int t = 0; t < 4; t++) {
                float w = cubicw(fz - (float)(z0 - 1 + t));
                int pz = min(max(z0 - 1 + t, 0), pn - 1);
                if (tid < 8) { swx[tid][t] = w; spx[tid][t] = pz; }
                else         { swy[t] = w;     spy[t] = pz; }
            }
        }
        __syncthreads();
        float acc = 0.f;
        #pragma unroll
        for (int ty2 = 0; ty2 < 4; ty2++) {
            int py = spy[ty2];
            float rowacc = 0.f;
            #pragma unroll
            for (int tx2 = 0; tx2 < 4; tx2++) {
                int px = spx[tyi][tx2];
                int n = (b*pn + py)*pn + px;
                int idx = (int)(0xFFFFFFFFu - (unsigned)(g_keys[n] & 0xFFFFFFFFull));
                rowacc += swx[tyi][tx2]*cb[idx*CC + c];
            }
            acc += swy[ty2]*rowacc;
        }
        out = acc;
    }
    g_hup[((b*CC + c)*HH + Y)*HH + X] = out;
}

// -------- conv3x3 + Phi blend + update + loss partial (oc-pair f32x2) --------
// grid (16 ytiles, 8 b, 2 oc-halves), block (64,4), dynamic smem.
#define CONV_SMEM ((32*6*66 + 8*32*9*2 + 16 + 256)*4)

__global__ void k_conv(const float* __restrict__ f, const float* __restrict__ phi_w,
                       const float* __restrict__ phi_b, float* __restrict__ fhat,
                       int kphi, int si) {
    extern __shared__ float sh[];
    float* tile  = sh;                    // 32*6*66 = 12672 floats
    float* wsh2f = tile + 32*6*66;        // 8 ocpair * 32 ic * 9 tap * 2 = 4608 floats
    float* bsh   = wsh2f + 8*32*9*2;      // 16
    float* red   = bsh + 16;              // 256
    int tx = threadIdx.x, ty = threadIdx.y;
    int tid = ty*64 + tx;
    int y0 = blockIdx.x*4;
    int b  = blockIdx.y;
    int ocb = blockIdx.z*16;

    // interleave weights: wsh2f[((op*32+ic)*9+t)*2 + h] = w[ocb+2op+h][ic][t]
    const float* wsrc = phi_w + (size_t)(kphi*32 + ocb)*32*9;
    for (int i = tid; i < 8*32*9; i += 256) {
        int op = i / 288; int rem = i % 288;
        wsh2f[2*i]     = wsrc[(2*op)*288 + rem];
        wsh2f[2*i + 1] = wsrc[(2*op + 1)*288 + rem];
    }
    if (tid < 16) bsh[tid] = phi_b[kphi*32 + ocb + tid];

    for (int i = tid; i < 32*6*66; i += 256) {
        int xx = i % 66; int yy = (i/66) % 6; int ic = i/(66*6);
        int gy = y0 - 1 + yy, gx = xx - 1;
        float val = 0.f;
        if ((unsigned)gy < 64u && (unsigned)gx < 64u)
            val = g_hup[((b*CC + ic)*HH + gy)*HH + gx];
        tile[i] = val;
    }
    __syncthreads();

    const ull* wsh2 = (const ull*)wsh2f;
    ull acc2[8];
    #pragma unroll
    for (int op = 0; op < 8; op++) acc2[op] = 0ull;

    for (int ic = 0; ic < 32; ic++) {
        const float* tb = tile + (ic*6 + ty)*66 + tx;
        ull td0 = pack2(tb[0],   tb[0]),   td1 = pack2(tb[1],   tb[1]),   td2 = pack2(tb[2],   tb[2]);
        ull td3 = pack2(tb[66],  tb[66]),  td4 = pack2(tb[67],  tb[67]),  td5 = pack2(tb[68],  tb[68]);
        ull td6 = pack2(tb[132], tb[132]), td7 = pack2(tb[133], tb[133]), td8 = pack2(tb[134], tb[134]);
        #pragma unroll
        for (int op = 0; op < 8; op++) {
            const ull* w = wsh2 + (op*32 + ic)*9;
            ull a = acc2[op];
            a = fma2(td0, w[0], a); a = fma2(td1, w[1], a); a = fma2(td2, w[2], a);
            a = fma2(td3, w[3], a); a = fma2(td4, w[4], a); a = fma2(td5, w[5], a);
            a = fma2(td6, w[6], a); a = fma2(td7, w[7], a); a = fma2(td8, w[8], a);
            acc2[op] = a;
        }
    }

    float ss = 0.f;
    int y = y0 + ty, x = tx;
    #pragma unroll
    for (int op = 0; op < 8; op++) {
        float aLo, aHi;
        unpack2(acc2[op], aLo, aHi);
        #pragma unroll
        for (int hh = 0; hh < 2; hh++) {
            int o = 2*op + hh;
            float a = hh ? aHi : aLo;
            int oc = ocb + o;
            float h  = tile[(oc*6 + ty + 1)*66 + tx + 1];
            float hp = 0.5f*h + 0.5f*(a + bsh[o]);
            int gi = ((b*CC + oc)*HH + y)*HH + x;
            float fv = f[gi];
            float fh = (si == 0 ? 0.f : fhat[gi]) + hp;
            fhat[gi] = fh;
            g_frest[gi] = fv - fh;
            float d = fh - fv;
            ss += d*d;
        }
    }

    red[tid] = ss;
    __syncthreads();
    #pragma unroll
    for (int s = 128; s > 0; s >>= 1) {
        if (tid < s) red[tid] += red[tid + s];
        __syncthreads();
    }
    if (tid == 0) {
        int bl = (blockIdx.z*8 + blockIdx.y)*16 + blockIdx.x;
        g_partials[si*256 + bl] = red[0];
    }
}

// -------- final loss reduce (deterministic fixed order) --------
__global__ void k_final(float* __restrict__ out) {
    __shared__ float red[128];
    int tid = threadIdx.x;
    float s = 0.f;
    for (int i = tid; i < NSCALE*256; i += 128) s += g_partials[i];
    red[tid] = s;
    __syncthreads();
    #pragma unroll
    for (int st = 64; st > 0; st >>= 1) {
        if (tid < st) red[tid] += red[tid + st];
        __syncthreads();
    }
    if (tid == 0) {
        float T = red[0];
        out[NELEM]     = T / (7.f * (float)NELEM);
        out[NELEM + 1] = 0.25f * T / (float)NELEM;
    }
}

// -------- host --------
extern "C" void kernel_launch(void* const* d_in, const int* in_sizes, int n_in,
                              void* d_out, int out_size) {
    const float* f    = (const float*)d_in[0];
    const float* cb   = (const float*)d_in[1];
    const float* phiw = (const float*)d_in[2];
    const float* phib = (const float*)d_in[3];
    float* out = (float*)d_out;

    cudaFuncSetAttribute(k_conv, cudaFuncAttributeMaxDynamicSharedMemorySize, CONV_SMEM);

    void *keysPtr = nullptr, *frestPtr = nullptr, *restPtr = nullptr;
    cudaGetSymbolAddress(&keysPtr, g_keys);
    cudaGetSymbolAddress(&frestPtr, g_frest);
    cudaGetSymbolAddress(&restPtr, g_rest);

    k_cbn<<<(VOCABN*32 + 255)/256, 256>>>(cb);

    const int pns[NSCALE]    = {1, 2, 4, 8, 16, 32, 64};
    // PHI ticks in float64: si=3 (key 0.5) resolves to phi index 2 (fp tie-break), NOT 1.
    const int phiIdx[NSCALE] = {0, 0, 1, 2, 2, 3, 3};
    // chunks MUST be multiples of 256 (k_argmax_big scans full 256-code tiles)
    const int chunks[NSCALE] = {0, 0, 0, 256, 256, 512, 2048};

    for (int si = 0; si < NSCALE; si++) {
        int pn = pns[si]; int pnpn = pn*pn; int N = BB*pnpn; int k = HH/pn;
        const float* src = (si == 0) ? f : (const float*)frestPtr;
        const float* restp;
        if (pn == HH) {
            restp = src;  // last scale: residual used directly
        } else {
            int outs = N*CC;
            if (k <= 4) k_ds_thread<<<(outs + 255)/256, 256>>>(src, pn, k);
            else        k_ds_warp<<<(outs*32 + 255)/256, 256>>>(src, pn, k);
            restp = (const float*)restPtr;
        }
        if (N <= 128) {
            k_argmax_small<<<N, 512>>>(restp, pnpn);
        } else {
            cudaMemsetAsync(keysPtr, 0, (size_t)N*sizeof(ull));
            dim3 g((N + 127)/128, VOCABN/chunks[si]);
            k_argmax_big<<<g, 128>>>(restp, N, pnpn, chunks[si]);
        }
        k_up<<<dim3(8, 64, 8), dim3(32, 8)>>>(cb, pn);
        k_conv<<<dim3(16, 8, 2), dim3(64, 4), CONV_SMEM>>>(f, phiw, phib, out, phiIdx[si], si);
    }
    k_final<<<1, 128>>>(out);
}

// round 6
// speedup vs baseline: 1.2953x; 1.0265x over previous
#include <cuda_runtime.h>

#define BB 8
#define CC 32
#define HH 64
#define VOCABN 4096
#define NELEM (BB*CC*HH*HH)   // 131072
#define NSCALE 7
#define NKEYS 43688           // sum of B*pn*pn over all scales

typedef unsigned long long ull;

// -------- scratch (static __device__, no allocations) --------
__device__ float g_cbn[VOCABN*CC];            // normalized codebook, PAIR-INTERLEAVED:
                                              // g_cbn[p*64 + 2*c + h] = cbn[2p+h][c]
__device__ float g_frest[NELEM];              // running residual
__device__ float g_rest[BB*CC*32*32];         // downsampled residual (pn=8..32)
__device__ float g_hup[NELEM];                // upsampled gathered codes
__device__ ull g_keys[NKEYS];                 // packed (sim,idx) keys, per-scale offsets
__device__ float g_partials[NSCALE*256];      // per-block loss partials

// -------- f32x2 packed math (sm_100+) --------
__device__ __forceinline__ ull fma2(ull a, ull b, ull c) {
    ull d; asm("fma.rn.f32x2 %0, %1, %2, %3;" : "=l"(d) : "l"(a), "l"(b), "l"(c)); return d;
}
__device__ __forceinline__ ull add2(ull a, ull b) {
    ull d; asm("add.rn.f32x2 %0, %1, %2;" : "=l"(d) : "l"(a), "l"(b)); return d;
}
__device__ __forceinline__ ull pack2(float lo, float hi) {
    ull d; asm("mov.b64 %0, {%1, %2};" : "=l"(d) : "f"(lo), "f"(hi)); return d;
}
__device__ __forceinline__ void unpack2(ull v, float& lo, float& hi) {
    asm("mov.b64 {%0, %1}, %2;" : "=f"(lo), "=f"(hi) : "l"(v));
}

__device__ __forceinline__ unsigned f2ord(float f) {
    unsigned u = __float_as_uint(f);
    return (u & 0x80000000u) ? ~u : (u | 0x80000000u);
}

// -------- codebook row-normalize -> pair-interleaved layout --------
__global__ void k_cbn(const float* __restrict__ cb) {
    int row = (blockIdx.x*blockDim.x + threadIdx.x) >> 5;
    int lane = threadIdx.x & 31;
    if (row >= VOCABN) return;
    float v = cb[row*CC + lane];
    float s = v*v;
    #pragma unroll
    for (int o = 16; o; o >>= 1) s += __shfl_xor_sync(0xffffffffu, s, o);
    int p = row >> 1, h = row & 1;
    g_cbn[p*64 + 2*lane + h] = v / sqrtf(s);
}

// -------- area downsample, thread per output (k <= 4) --------
__global__ void k_ds_thread(const float* __restrict__ src, int pn, int k) {
    int i = blockIdx.x*blockDim.x + threadIdx.x;
    int total = BB*CC*pn*pn;
    if (i >= total) return;
    int q = i % pn; int p = (i/pn) % pn; int bc = i/(pn*pn);
    const float* s = src + bc*HH*HH + p*k*HH + q*k;
    float acc = 0.f;
    for (int yy = 0; yy < k; yy++)
        for (int xx = 0; xx < k; xx++) acc += s[yy*HH + xx];
    g_rest[i] = acc * (1.f/(float)(k*k));
}

// -------- area downsample, warp per output (k >= 8) --------
__global__ void k_ds_warp(const float* __restrict__ src, int pn, int k) {
    int gw = (blockIdx.x*blockDim.x + threadIdx.x) >> 5;
    int lane = threadIdx.x & 31;
    int total = BB*CC*pn*pn;
    if (gw >= total) return;
    int q = gw % pn; int p = (gw/pn) % pn; int bc = gw/(pn*pn);
    const float* s = src + bc*HH*HH + p*k*HH + q*k;
    int kk = k*k;
    float acc = 0.f;
    for (int t = lane; t < kk; t += 32) acc += s[(t/k)*HH + (t % k)];
    #pragma unroll
    for (int o = 16; o; o >>= 1) acc += __shfl_xor_sync(0xffffffffu, acc, o);
    if (lane == 0) g_rest[gw] = acc * (1.f/(float)kk);
}

// -------- pair dot-product core: 32 channels vs packed code pair --------
__device__ __forceinline__ void pair_sim(const ull* __restrict__ vd,
                                         const float* __restrict__ pairrow,
                                         float& lo, float& hi) {
    const ulonglong2* row2 = (const ulonglong2*)pairrow;
    ull a0 = 0ull, a1 = 0ull, a2 = 0ull, a3 = 0ull;
    #pragma unroll
    for (int cc = 0; cc < 8; cc++) {
        ulonglong2 r0 = row2[2*cc];
        ulonglong2 r1 = row2[2*cc+1];
        a0 = fma2(vd[4*cc+0], r0.x, a0);
        a1 = fma2(vd[4*cc+1], r0.y, a1);
        a2 = fma2(vd[4*cc+2], r1.x, a2);
        a3 = fma2(vd[4*cc+3], r1.y, a3);
    }
    ull s = add2(add2(a0, a1), add2(a2, a3));
    unpack2(s, lo, hi);
}

// -------- argmax with FUSED area-downsample, block per vector (pn<=4) --------
__global__ void k_argmax_small(const float* __restrict__ src, int pn, int k, int koff) {
    __shared__ float psum[512];
    __shared__ float vsh[CC];
    __shared__ ull kred[512];
    int n = blockIdx.x;
    int tid = threadIdx.x;
    int pnpn = pn*pn;
    int b = n / pnpn, r = n % pnpn;
    int p = r / pn, q = r % pn;
    // fused patch mean: channel c = tid>>4, 16 partial-sum threads per channel
    {
        int c = tid >> 4, sub = tid & 15;
        const float* sp = src + (b*CC + c)*HH*HH + p*k*HH + q*k;
        int kk = k*k;
        float a = 0.f;
        for (int t = sub; t < kk; t += 16) a += sp[(t/k)*HH + (t%k)];
        psum[tid] = a;
        __syncthreads();
        if (sub == 0) {
            float s = 0.f;
            #pragma unroll
            for (int u = 0; u < 16; u++) s += psum[(c<<4) + u];
            vsh[c] = s * (1.f/(float)kk);
        }
        __syncthreads();
    }
    ull vd[CC];
    #pragma unroll
    for (int c = 0; c < CC; c++) { float v = vsh[c]; vd[c] = pack2(v, v); }
    float best = -1e30f; int bidx = 0;
    for (int pr = tid; pr < VOCABN/2; pr += 512) {
        float lo, hi;
        pair_sim(vd, g_cbn + pr*64, lo, hi);
        if (lo > best) { best = lo; bidx = 2*pr; }
        if (hi > best) { best = hi; bidx = 2*pr + 1; }
    }
    kred[tid] = ((ull)f2ord(best) << 32) | (ull)(0xFFFFFFFFu - (unsigned)bidx);
    __syncthreads();
    #pragma unroll
    for (int s = 256; s > 0; s >>= 1) {
        if (tid < s) { ull o = kred[tid+s]; if (o > kred[tid]) kred[tid] = o; }
        __syncthreads();
    }
    if (tid == 0) g_keys[koff + n] = kred[0];
}

// -------- argmax, thread per vector, codes split across blockIdx.y --------
// REQUIREMENT: chunk must be a multiple of 256 (full tiles only).
__global__ void k_argmax_big(const float* __restrict__ rest, int N, int pnpn,
                             int chunk, int koff) {
    __shared__ float scb[256*CC];  // 32 KB tile: 128 pairs x 64 floats
    int n = blockIdx.x*128 + threadIdx.x;
    int c0 = blockIdx.y * chunk;
    ull vd[CC];
    bool active = (n < N);
    if (active) {
        int b = n / pnpn, r = n % pnpn;
        const float* s = rest + b*CC*pnpn + r;
        #pragma unroll
        for (int c = 0; c < CC; c++) { float v = s[c*pnpn]; vd[c] = pack2(v, v); }
    } else {
        #pragma unroll
        for (int c = 0; c < CC; c++) vd[c] = 0ull;
    }
    float best = -1e30f; int bidx = 0;
    for (int t0 = 0; t0 < chunk; t0 += 256) {
        __syncthreads();
        const float4* src4 = (const float4*)(g_cbn + (c0 + t0)*CC);
        float4* dst4 = (float4*)scb;
        #pragma unroll 4
        for (int i = threadIdx.x; i < 256*8; i += 128) dst4[i] = src4[i];
        __syncthreads();
        #pragma unroll 4
        for (int j2 = 0; j2 < 128; j2++) {
            float lo, hi;
            pair_sim(vd, scb + j2*64, lo, hi);
            int code = c0 + t0 + 2*j2;
            if (lo > best) { best = lo; bidx = code; }
            if (hi > best) { best = hi; bidx = code + 1; }
        }
    }
    if (active) {
        ull key = ((ull)f2ord(best) << 32) | (ull)(0xFFFFFFFFu - (unsigned)bidx);
        atomicMax(g_keys + koff + n, key);
    }
}

// -------- bicubic weight (PyTorch A=-0.75) --------
__device__ __forceinline__ float cubicw(float t) {
    t = fabsf(t);
    float t2 = t*t, t3 = t2*t;
    if (t <= 1.f) return 1.25f*t3 - 2.25f*t2 + 1.f;
    if (t < 2.f)  return -0.75f*t3 + 3.75f*t2 - 6.f*t + 3.f;
    return 0.f;
}

// -------- gather + bicubic upsample (or direct gather for pn==64) --------
// MLP-batched gathers + smem transpose for coalesced g_hup stores.
__global__ __launch_bounds__(256) void k_up(const float* __restrict__ cb, int pn, int koff) {
    __shared__ float swx[8][4];
    __shared__ int   spx[8][4];
    __shared__ float swy[4];
    __shared__ int   spy[4];
    __shared__ float st[8][33];
    int c = threadIdx.x;                    // 0..31 (channel)
    int tyi = threadIdx.y;                  // 0..7
    int X0 = blockIdx.x*8;
    int X = X0 + tyi;                       // 0..63
    int Y = blockIdx.y;                     // 0..63
    int b = blockIdx.z;                     // 0..7
    int tid = tyi*32 + c;
    const ull* keys = g_keys + koff;
    float out;
    if (pn == HH) {
        int n = (b*HH + Y)*HH + X;
        int idx = (int)(0xFFFFFFFFu - (unsigned)(keys[n] & 0xFFFFFFFFull));
        out = cb[idx*CC + c];
    } else {
        if (tid < 9) {
            float scale = (float)pn / (float)HH;
            int pos = (tid < 8) ? (X0 + tid) : Y;
            float fz = (pos + 0.5f)*scale - 0.5f;
            int z0 = (int)floorf(fz);
            #pragma unroll
            for (int t = 0; t < 4; t++) {
                float w = cubicw(fz - (float)(z0 - 1 + t));
                int pz = min(max(z0 - 1 + t, 0), pn - 1);
                if (tid < 8) { swx[tid][t] = w; spx[tid][t] = pz; }
                else         { swy[t] = w;     spy[t] = pz; }
            }
        }
        __syncthreads();
        // batch all 16 gathers (independent -> MLP 16)
        int nb = b*pn*pn;
        float vals[16];
        #pragma unroll
        for (int t = 0; t < 16; t++) {
            int py = spy[t >> 2], px = spx[tyi][t & 3];
            int idx = (int)(0xFFFFFFFFu - (unsigned)(keys[nb + py*pn + px] & 0xFFFFFFFFull));
            vals[t] = cb[idx*CC + c];
        }
        float acc = 0.f;
        #pragma unroll
        for (int t2 = 0; t2 < 4; t2++) {
            float rowacc = vals[t2*4+0]*swx[tyi][0] + vals[t2*4+1]*swx[tyi][1]
                         + vals[t2*4+2]*swx[tyi][2] + vals[t2*4+3]*swx[tyi][3];
            acc += swy[t2]*rowacc;
        }
        out = acc;
    }
    st[tyi][c] = out;
    __syncthreads();
    // coalesced store: warp writes 4 channels x 8 consecutive X
    int c2 = tid >> 3, x2 = tid & 7;
    g_hup[(b*CC + c2)*HH*HH + Y*HH + X0 + x2] = st[x2][c2];
}

// -------- conv3x3 + Phi blend + update + loss partial (oc-pair f32x2) --------
// grid (16 ytiles, 8 b, 2 oc-halves), block (64,4), dynamic smem.
#define CONV_SMEM ((32*6*66 + 8*32*9*2 + 16 + 256)*4)

__global__ void k_conv(const float* __restrict__ f, const float* __restrict__ phi_w,
                       const float* __restrict__ phi_b, float* __restrict__ fhat,
                       int kphi, int si) {
    extern __shared__ float sh[];
    float* tile  = sh;                    // 32*6*66 = 12672 floats
    float* wsh2f = tile + 32*6*66;        // 8 ocpair * 32 ic * 9 tap * 2 = 4608 floats
    float* bsh   = wsh2f + 8*32*9*2;      // 16
    float* red   = bsh + 16;              // 256
    int tx = threadIdx.x, ty = threadIdx.y;
    int tid = ty*64 + tx;
    int y0 = blockIdx.x*4;
    int b  = blockIdx.y;
    int ocb = blockIdx.z*16;

    // interleave weights: wsh2f[((op*32+ic)*9+t)*2 + h] = w[ocb+2op+h][ic][t]
    const float* wsrc = phi_w + (size_t)(kphi*32 + ocb)*32*9;
    for (int i = tid; i < 8*32*9; i += 256) {
        int op = i / 288; int rem = i % 288;
        wsh2f[2*i]     = wsrc[(2*op)*288 + rem];
        wsh2f[2*i + 1] = wsrc[(2*op + 1)*288 + rem];
    }
    if (tid < 16) bsh[tid] = phi_b[kphi*32 + ocb + tid];

    for (int i = tid; i < 32*6*66; i += 256) {
        int xx = i % 66; int yy = (i/66) % 6; int ic = i/(66*6);
        int gy = y0 - 1 + yy, gx = xx - 1;
        float val = 0.f;
        if ((unsigned)gy < 64u && (unsigned)gx < 64u)
            val = g_hup[((b*CC + ic)*HH + gy)*HH + gx];
        tile[i] = val;
    }
    __syncthreads();

    const ull* wsh2 = (const ull*)wsh2f;
    ull acc2[8];
    #pragma unroll
    for (int op = 0; op < 8; op++) acc2[op] = 0ull;

    for (int ic = 0; ic < 32; ic++) {
        const float* tb = tile + (ic*6 + ty)*66 + tx;
        ull td0 = pack2(tb[0],   tb[0]),   td1 = pack2(tb[1],   tb[1]),   td2 = pack2(tb[2],   tb[2]);
        ull td3 = pack2(tb[66],  tb[66]),  td4 = pack2(tb[67],  tb[67]),  td5 = pack2(tb[68],  tb[68]);
        ull td6 = pack2(tb[132], tb[132]), td7 = pack2(tb[133], tb[133]), td8 = pack2(tb[134], tb[134]);
        #pragma unroll
        for (int op = 0; op < 8; op++) {
            const ull* w = wsh2 + (op*32 + ic)*9;
            ull a = acc2[op];
            a = fma2(td0, w[0], a); a = fma2(td1, w[1], a); a = fma2(td2, w[2], a);
            a = fma2(td3, w[3], a); a = fma2(td4, w[4], a); a = fma2(td5, w[5], a);
            a = fma2(td6, w[6], a); a = fma2(td7, w[7], a); a = fma2(td8, w[8], a);
            acc2[op] = a;
        }
    }

    float ss = 0.f;
    int y = y0 + ty, x = tx;
    #pragma unroll
    for (int op = 0; op < 8; op++) {
        float aLo, aHi;
        unpack2(acc2[op], aLo, aHi);
        #pragma unroll
        for (int hh = 0; hh < 2; hh++) {
            int o = 2*op + hh;
            float a = hh ? aHi : aLo;
            int oc = ocb + o;
            float h  = tile[(oc*6 + ty + 1)*66 + tx + 1];
            float hp = 0.5f*h + 0.5f*(a + bsh[o]);
            int gi = ((b*CC + oc)*HH + y)*HH + x;
            float fv = f[gi];
            float fh = (si == 0 ? 0.f : fhat[gi]) + hp;
            fhat[gi] = fh;
            g_frest[gi] = fv - fh;
            float d = fh - fv;
            ss += d*d;
        }
    }

    red[tid] = ss;
    __syncthreads();
    #pragma unroll
    for (int s = 128; s > 0; s >>= 1) {
        if (tid < s) red[tid] += red[tid + s];
        __syncthreads();
    }
    if (tid == 0) {
        int bl = (blockIdx.z*8 + blockIdx.y)*16 + blockIdx.x;
        g_partials[si*256 + bl] = red[0];
    }
}

// -------- final loss reduce (deterministic fixed order) --------
__global__ void k_final(float* __restrict__ out) {
    __shared__ float red[128];
    int tid = threadIdx.x;
    float s = 0.f;
    for (int i = tid; i < NSCALE*256; i += 128) s += g_partials[i];
    red[tid] = s;
    __syncthreads();
    #pragma unroll
    for (int st = 64; st > 0; st >>= 1) {
        if (tid < st) red[tid] += red[tid + st];
        __syncthreads();
    }
    if (tid == 0) {
        float T = red[0];
        out[NELEM]     = T / (7.f * (float)NELEM);
        out[NELEM + 1] = 0.25f * T / (float)NELEM;
    }
}

// -------- host --------
extern "C" void kernel_launch(void* const* d_in, const int* in_sizes, int n_in,
                              void* d_out, int out_size) {
    const float* f    = (const float*)d_in[0];
    const float* cb   = (const float*)d_in[1];
    const float* phiw = (const float*)d_in[2];
    const float* phib = (const float*)d_in[3];
    float* out = (float*)d_out;

    cudaFuncSetAttribute(k_conv, cudaFuncAttributeMaxDynamicSharedMemorySize, CONV_SMEM);

    void *keysPtr = nullptr, *frestPtr = nullptr, *restPtr = nullptr;
    cudaGetSymbolAddress(&keysPtr, g_keys);
    cudaGetSymbolAddress(&frestPtr, g_frest);
    cudaGetSymbolAddress(&restPtr, g_rest);

    // one upfront zero of the whole key buffer (covers all chunked-atomic scales)
    cudaMemsetAsync(keysPtr, 0, (size_t)NKEYS*sizeof(ull));
    k_cbn<<<(VOCABN*32 + 255)/256, 256>>>(cb);

    const int pns[NSCALE]    = {1, 2, 4, 8, 16, 32, 64};
    // PHI ticks in float64: si=3 (key 0.5) resolves to phi index 2 (fp tie-break), NOT 1.
    const int phiIdx[NSCALE] = {0, 0, 1, 2, 2, 3, 3};
    // chunks MUST be multiples of 256 (k_argmax_big scans full 256-code tiles)
    const int chunks[NSCALE] = {0, 0, 0, 256, 256, 512, 2048};
    // per-scale key offsets: prefix sums of N = 8*pn*pn
    const int koffs[NSCALE]  = {0, 8, 40, 168, 680, 2728, 10920};

    for (int si = 0; si < NSCALE; si++) {
        int pn = pns[si]; int pnpn = pn*pn; int N = BB*pnpn; int k = HH/pn;
        const float* src = (si == 0) ? f : (const float*)frestPtr;

        if (pn <= 4) {
            // fused downsample + argmax, block per vector
            k_argmax_small<<<N, 512>>>(src, pn, k, koffs[si]);
        } else {
            if (pn == HH) {
                // last scale: residual used directly
            } else {
                int outs = N*CC;
                if (k <= 4) k_ds_thread<<<(outs + 255)/256, 256>>>(src, pn, k);
                else        k_ds_warp<<<(outs*32 + 255)/256, 256>>>(src, pn, k);
            }
            const float* restp = (pn == HH) ? src : (const float*)restPtr;
            dim3 g((N + 127)/128, VOCABN/chunks[si]);
            k_argmax_big<<<g, 128>>>(restp, N, pnpn, chunks[si], koffs[si]);
        }
        k_up<<<dim3(8, 64, 8), dim3(32, 8)>>>(cb, pn, koffs[si]);
        k_conv<<<dim3(16, 8, 2), dim3(64, 4), CONV_SMEM>>>(f, phiw, phib, out, phiIdx[si], si);
    }
    k_final<<<1, 128>>>(out);
}